// round 2
// baseline (speedup 1.0000x reference)
#include <cuda_runtime.h>
#include <math.h>

#define BB 64
#define SS 4096
#define DD 256
#define WARPS_PER_CTA 8
#define CTAS_PER_BATCH 4
#define NPART (WARPS_PER_CTA * CTAS_PER_BATCH)          // 32 partials per batch
#define ROWS_PER_WARP (SS / NPART)                      // 128
#define LN_EPS 1e-3f

// Scratch for partial online-softmax state (no cudaMalloc allowed).
__device__ float g_part_m[BB * NPART];
__device__ float g_part_l[BB * NPART];
__device__ float g_part_acc[(size_t)BB * NPART * DD];

// ---------------------------------------------------------------------------
// Pass 1: one warp owns ROWS_PER_WARP contiguous rows of one batch.
// Per row: 3 warp reductions (sum x, sum x^2, sum x*gamma*w) -> LN score,
// then online-softmax accumulate x into register-resident acc[8]/lane.
// ---------------------------------------------------------------------------
__global__ void __launch_bounds__(WARPS_PER_CTA * 32, 2)
pass1_kernel(const float* __restrict__ x,
             const float* __restrict__ mask,
             const float* __restrict__ gamma,
             const float* __restrict__ beta,
             const float* __restrict__ w,
             const float* __restrict__ bias)
{
    const int cta   = blockIdx.x;
    const int batch = cta / CTAS_PER_BATCH;
    const int chunk = cta % CTAS_PER_BATCH;
    const int wid   = threadIdx.x >> 5;
    const int lane  = threadIdx.x & 31;
    const int part  = chunk * WARPS_PER_CTA + wid;       // 0..31 within batch
    const int row0  = part * ROWS_PER_WARP;

    // Each lane covers feature columns [4*lane, 4*lane+3] and [128+4*lane, ...+3]
    const int c0 = lane * 4;
    const int c1 = 128 + lane * 4;

    // Per-lane LN/Dense constants
    const float4 ga0 = *(const float4*)(gamma + c0);
    const float4 ga1 = *(const float4*)(gamma + c1);
    const float4 be0 = *(const float4*)(beta  + c0);
    const float4 be1 = *(const float4*)(beta  + c1);
    const float4 w0  = *(const float4*)(w + c0);
    const float4 w1  = *(const float4*)(w + c1);

    float gw[8];
    gw[0] = ga0.x * w0.x; gw[1] = ga0.y * w0.y; gw[2] = ga0.z * w0.z; gw[3] = ga0.w * w0.w;
    gw[4] = ga1.x * w1.x; gw[5] = ga1.y * w1.y; gw[6] = ga1.z * w1.z; gw[7] = ga1.w * w1.w;

    // gwsum = sum(gamma*w), bwb = sum(beta*w) + bias  (reduced once per warp)
    float gws = gw[0]+gw[1]+gw[2]+gw[3]+gw[4]+gw[5]+gw[6]+gw[7];
    float bwb = be0.x*w0.x + be0.y*w0.y + be0.z*w0.z + be0.w*w0.w
              + be1.x*w1.x + be1.y*w1.y + be1.z*w1.z + be1.w*w1.w;
    #pragma unroll
    for (int o = 16; o > 0; o >>= 1) {
        gws += __shfl_xor_sync(0xffffffffu, gws, o);
        bwb += __shfl_xor_sync(0xffffffffu, bwb, o);
    }
    bwb += bias[0];

    // Online-softmax state (register resident)
    float m = -INFINITY;
    float l = 0.0f;
    float acc[8];
    #pragma unroll
    for (int j = 0; j < 8; j++) acc[j] = 0.0f;

    const float* xbase = x + ((size_t)batch * SS + row0) * DD;
    const float* mbase = mask + (size_t)batch * SS + row0;
    const float inv_d = 1.0f / (float)DD;

    #pragma unroll 2
    for (int r = 0; r < ROWS_PER_WARP; r++) {
        const float4* xr = (const float4*)(xbase + (size_t)r * DD);
        float4 a = xr[lane];        // cols c0..c0+3  (coalesced 512B)
        float4 b = xr[32 + lane];   // cols c1..c1+3

        float xv[8] = {a.x, a.y, a.z, a.w, b.x, b.y, b.z, b.w};

        float s1 = 0.f, s2 = 0.f, sw = 0.f;
        #pragma unroll
        for (int j = 0; j < 8; j++) {
            s1 += xv[j];
            s2 = fmaf(xv[j], xv[j], s2);
            sw = fmaf(xv[j], gw[j], sw);
        }
        #pragma unroll
        for (int o = 16; o > 0; o >>= 1) {
            s1 += __shfl_xor_sync(0xffffffffu, s1, o);
            s2 += __shfl_xor_sync(0xffffffffu, s2, o);
            sw += __shfl_xor_sync(0xffffffffu, sw, o);
        }

        float mu   = s1 * inv_d;
        float var  = fmaf(-mu, mu, s2 * inv_d);
        float rstd = rsqrtf(var + LN_EPS);
        float score = fmaf(rstd, sw - mu * gws, bwb);
        score = fmaf(1.0f - mbase[r], -1e9f, score);

        // Online softmax update
        float mn   = fmaxf(m, score);
        float corr = __expf(m - mn);
        float e    = __expf(score - mn);
        l = fmaf(l, corr, e);
        m = mn;
        #pragma unroll
        for (int j = 0; j < 8; j++)
            acc[j] = fmaf(acc[j], corr, e * xv[j]);
    }

    // Write partials
    const int pidx = batch * NPART + part;
    if (lane == 0) { g_part_m[pidx] = m; g_part_l[pidx] = l; }
    float* dst = g_part_acc + (size_t)pidx * DD;
    float4 o0 = {acc[0], acc[1], acc[2], acc[3]};
    float4 o1 = {acc[4], acc[5], acc[6], acc[7]};
    *(float4*)(dst + c0) = o0;
    *(float4*)(dst + c1) = o1;
}

// ---------------------------------------------------------------------------
// Pass 2: combine the 32 partials per batch. One CTA per batch, 256 threads
// (one per feature d).
// ---------------------------------------------------------------------------
__global__ void __launch_bounds__(DD)
pass2_kernel(float* __restrict__ out)
{
    const int batch = blockIdx.x;
    const int t = threadIdx.x;

    __shared__ float sm[NPART];
    __shared__ float sl[NPART];
    __shared__ float sscale[NPART];

    if (t < NPART) {
        sm[t] = g_part_m[batch * NPART + t];
        sl[t] = g_part_l[batch * NPART + t];
    }
    __syncthreads();

    float M = -INFINITY;
    #pragma unroll
    for (int i = 0; i < NPART; i++) M = fmaxf(M, sm[i]);

    if (t < NPART) sscale[t] = __expf(sm[t] - M);
    __syncthreads();

    float L = 0.0f;
    #pragma unroll
    for (int i = 0; i < NPART; i++) L = fmaf(sl[i], sscale[i], L);

    const float* accb = g_part_acc + (size_t)batch * NPART * DD;
    float v = 0.0f;
    #pragma unroll
    for (int i = 0; i < NPART; i++)
        v = fmaf(accb[(size_t)i * DD + t], sscale[i], v);

    out[batch * DD + t] = v / L;
}

// ---------------------------------------------------------------------------
extern "C" void kernel_launch(void* const* d_in, const int* in_sizes, int n_in,
                              void* d_out, int out_size)
{
    const float* x     = (const float*)d_in[0];
    const float* mask  = (const float*)d_in[1];
    const float* gamma = (const float*)d_in[2];
    const float* beta  = (const float*)d_in[3];
    const float* w     = (const float*)d_in[4];
    const float* bias  = (const float*)d_in[5];
    float* out = (float*)d_out;

    pass1_kernel<<<BB * CTAS_PER_BATCH, WARPS_PER_CTA * 32>>>(x, mask, gamma, beta, w, bias);
    pass2_kernel<<<BB, DD>>>(out);
}

// round 6
// speedup vs baseline: 1.3805x; 1.3805x over previous
#include <cuda_runtime.h>
#include <math.h>

#define BB 64
#define SS 4096
#define DD 256
#define WARPS 8
#define CPB 4                      // CTAs per batch
#define GROUPS 4                   // 8-lane groups per warp
#define PARTS (CPB*WARPS*GROUPS)   // 128 partials per batch
#define RPG (SS/PARTS)             // 32 rows per group
#define LN_EPS 1e-3f

// Scratch (no cudaMalloc allowed)
__device__ float g_part_m[BB * PARTS];
__device__ float g_part_l[BB * PARTS];
__device__ float g_part_acc[(size_t)BB * PARTS * DD];

// ---------------------------------------------------------------------------
// Pass 1: each warp = 4 independent 8-lane groups; each group runs its own
// online-softmax chain over 32 rows. Reductions are 3-level 8-lane butterflies
// (one SHFL instruction covers all 4 groups at once).
// Lane layout: g = lane>>3 picks the row, p = lane&7 picks columns
// col4 index = p + 8j (j = 0..7), i.e. cols 4p+32j .. 4p+32j+3.
// ---------------------------------------------------------------------------
__global__ void __launch_bounds__(256, 2)
pass1_kernel(const float* __restrict__ x,
             const float* __restrict__ mask,
             const float* __restrict__ gamma,
             const float* __restrict__ beta,
             const float* __restrict__ w,
             const float* __restrict__ bias)
{
    const int cta   = blockIdx.x;
    const int batch = cta / CPB;
    const int chunk = cta % CPB;
    const int wid   = threadIdx.x >> 5;
    const int lane  = threadIdx.x & 31;
    const int g     = lane >> 3;
    const int p     = lane & 7;

    // Per-lane LN/Dense constants over the 32 owned columns
    float gw[32];
    float gws = 0.0f, bw = 0.0f;
    #pragma unroll
    for (int j = 0; j < 8; j++) {
        float4 ga = ((const float4*)gamma)[p + 8*j];
        float4 ww = ((const float4*)w)[p + 8*j];
        float4 be = ((const float4*)beta)[p + 8*j];
        gw[4*j+0] = ga.x * ww.x;  gw[4*j+1] = ga.y * ww.y;
        gw[4*j+2] = ga.z * ww.z;  gw[4*j+3] = ga.w * ww.w;
        gws += gw[4*j+0] + gw[4*j+1] + gw[4*j+2] + gw[4*j+3];
        bw  += be.x*ww.x + be.y*ww.y + be.z*ww.z + be.w*ww.w;
    }
    #pragma unroll
    for (int off = 4; off > 0; off >>= 1) {
        gws += __shfl_xor_sync(0xffffffffu, gws, off);
        bw  += __shfl_xor_sync(0xffffffffu, bw,  off);
    }
    bw += bias[0];

    // This group's row range
    const int row0 = chunk * (SS / CPB) + wid * (SS / CPB / WARPS) + g * RPG;
    const int part = chunk * (WARPS * GROUPS) + wid * GROUPS + g;

    const float* xbase = x + ((size_t)batch * SS + row0) * DD;
    const float* mbase = mask + (size_t)batch * SS + row0;
    const float inv_d  = 1.0f / (float)DD;

    float m = -INFINITY;
    float l = 0.0f;
    float acc[32];
    #pragma unroll
    for (int i = 0; i < 32; i++) acc[i] = 0.0f;

    for (int r = 0; r < RPG; r++) {
        const float4* xr = (const float4*)(xbase + (size_t)r * DD);
        float4 a[8];
        #pragma unroll
        for (int j = 0; j < 8; j++) a[j] = xr[p + 8*j];
        float mk = __ldg(mbase + r);

        float s1 = 0.f, s2 = 0.f, sw = 0.f;
        #pragma unroll
        for (int j = 0; j < 8; j++) {
            s1 += a[j].x + a[j].y + a[j].z + a[j].w;
            s2 = fmaf(a[j].x, a[j].x, s2); s2 = fmaf(a[j].y, a[j].y, s2);
            s2 = fmaf(a[j].z, a[j].z, s2); s2 = fmaf(a[j].w, a[j].w, s2);
            sw = fmaf(a[j].x, gw[4*j+0], sw); sw = fmaf(a[j].y, gw[4*j+1], sw);
            sw = fmaf(a[j].z, gw[4*j+2], sw); sw = fmaf(a[j].w, gw[4*j+3], sw);
        }
        // 8-lane butterfly (offsets 4,2,1 stay inside the group)
        #pragma unroll
        for (int off = 4; off > 0; off >>= 1) {
            s1 += __shfl_xor_sync(0xffffffffu, s1, off);
            s2 += __shfl_xor_sync(0xffffffffu, s2, off);
            sw += __shfl_xor_sync(0xffffffffu, sw, off);
        }

        float mu    = s1 * inv_d;
        float var   = fmaf(-mu, mu, s2 * inv_d);
        float rstd  = rsqrtf(var + LN_EPS);
        float score = fmaf(rstd, sw - mu * gws, bw);
        score = fmaf(1.0f - mk, -1e9f, score);

        float mn   = fmaxf(m, score);
        float corr = __expf(m - mn);
        float e    = __expf(score - mn);
        l = fmaf(l, corr, e);
        m = mn;
        #pragma unroll
        for (int j = 0; j < 8; j++) {
            acc[4*j+0] = fmaf(acc[4*j+0], corr, e * a[j].x);
            acc[4*j+1] = fmaf(acc[4*j+1], corr, e * a[j].y);
            acc[4*j+2] = fmaf(acc[4*j+2], corr, e * a[j].z);
            acc[4*j+3] = fmaf(acc[4*j+3], corr, e * a[j].w);
        }
    }

    // Write partials
    const int bidx = batch * PARTS + part;
    if (p == 0) { g_part_m[bidx] = m; g_part_l[bidx] = l; }
    float4* dst = (float4*)(g_part_acc + (size_t)bidx * DD);
    #pragma unroll
    for (int j = 0; j < 8; j++)
        dst[p + 8*j] = make_float4(acc[4*j+0], acc[4*j+1], acc[4*j+2], acc[4*j+3]);
}

// ---------------------------------------------------------------------------
// Pass 2: combine 128 partials per batch. 1024 threads: 4 segments x 256 cols
// for 4x memory-level parallelism, then smem reduce.
// ---------------------------------------------------------------------------
__global__ void __launch_bounds__(1024)
pass2_kernel(float* __restrict__ out)
{
    const int batch = blockIdx.x;
    const int t   = threadIdx.x;
    const int col = t & 255;
    const int seg = t >> 8;

    __shared__ float sm[PARTS];
    __shared__ float sprod[PARTS];
    __shared__ float sscale[PARTS];
    __shared__ float red[1024];

    if (t < PARTS) {
        sm[t]    = g_part_m[batch * PARTS + t];
        sprod[t] = g_part_l[batch * PARTS + t];
    }
    __syncthreads();

    float M = -INFINITY;
    #pragma unroll 8
    for (int i = 0; i < PARTS; i++) M = fmaxf(M, sm[i]);

    if (t < PARTS) {
        float sc = __expf(sm[t] - M);
        sscale[t] = sc;
        sprod[t] *= sc;
    }
    __syncthreads();

    float L = 0.0f;
    #pragma unroll 8
    for (int i = 0; i < PARTS; i++) L += sprod[i];

    const float* accb = g_part_acc + (size_t)batch * PARTS * DD;
    float v = 0.0f;
    #pragma unroll 8
    for (int i = seg * 32; i < seg * 32 + 32; i++)
        v = fmaf(accb[(size_t)i * DD + col], sscale[i], v);

    red[t] = v;
    __syncthreads();
    if (t < 256)
        out[batch * DD + t] = (red[t] + red[t + 256] + red[t + 512] + red[t + 768]) / L;
}

// ---------------------------------------------------------------------------
extern "C" void kernel_launch(void* const* d_in, const int* in_sizes, int n_in,
                              void* d_out, int out_size)
{
    const float* x     = (const float*)d_in[0];
    const float* mask  = (const float*)d_in[1];
    const float* gamma = (const float*)d_in[2];
    const float* beta  = (const float*)d_in[3];
    const float* w     = (const float*)d_in[4];
    const float* bias  = (const float*)d_in[5];
    float* out = (float*)d_out;

    pass1_kernel<<<BB * CPB, 256>>>(x, mask, gamma, beta, w, bias);
    pass2_kernel<<<BB, 1024>>>(out);
}